// round 5
// baseline (speedup 1.0000x reference)
#include <cuda_runtime.h>
#include <cstdint>

// InstantNGP: hash-grid encode + MLP 32->64->64->3 via warp-level tf32 mma.sync.
// Round-5 changes: 2-tile M-batching (32 pts/warp-iter) sharing B-fragment loads,
// swizzled 32-row scratch (dynamic smem, 4 CTA/SM), packed w2 epilogue loads.

namespace {

constexpr int S_DIM   = 1024;
constexpr int NPTS    = S_DIM * S_DIM;
constexpr int TBL     = 1 << 19;

constexpr int WARPS   = 4;
constexpr int THREADS = WARPS * 32;
constexpr int PPI     = 32;               // points per warp-iteration (2 M-tiles)
constexpr int ITERS   = 4;                // iterations per warp
constexpr int PPW     = PPI * ITERS;      // 128 points per warp
constexpr int GRID    = NPTS / (PPW * WARPS);   // 2048
constexpr int SCR_ROWS = 32;              // scratch rows per warp
constexpr int DYN_SMEM = WARPS * SCR_ROWS * 64 * 4;   // 32 KB

__device__ __forceinline__ uint32_t tf32_rna(float x) {
    uint32_t r;
    asm("cvt.rna.tf32.f32 %0, %1;" : "=r"(r) : "f"(x));
    return r;
}

// swizzled scratch addressing: conflict-free A-fragment reads at stride 64
__device__ __forceinline__ int sx(int row, int col) {
    return row * 64 + (col ^ ((row & 7) << 2));
}

__device__ __forceinline__ void mma8(float* d,
                                     uint32_t a0, uint32_t a1, uint32_t a2, uint32_t a3,
                                     uint32_t b0, uint32_t b1) {
    asm volatile(
        "mma.sync.aligned.m16n8k8.row.col.f32.tf32.tf32.f32 "
        "{%0,%1,%2,%3},{%4,%5,%6,%7},{%8,%9},{%0,%1,%2,%3};"
        : "+f"(d[0]), "+f"(d[1]), "+f"(d[2]), "+f"(d[3])
        : "r"(a0), "r"(a1), "r"(a2), "r"(a3), "r"(b0), "r"(b1));
}

__global__ __launch_bounds__(THREADS) void ngp_mma_kernel(
    const float2* __restrict__ xy,
    const float2* __restrict__ tab,
    const float*  __restrict__ W0,     // (32, 64) [k][n]
    const float*  __restrict__ W1,     // (64, 64) [k][n]
    const float*  __restrict__ W2,     // (64, 3)
    float*        __restrict__ out)    // (3, S, S)
{
    __shared__ uint2 w0f[4 * 8 * 32];   //  8 KB  B frags layer0
    __shared__ uint2 w1f[8 * 8 * 32];   // 16 KB  B frags layer1
    __shared__ float w2s[3 * 64];       // packed [j][c]
    extern __shared__ uint32_t dynscr[];

    const int tid = threadIdx.x;

    // ---- stage weights in fragment order (once per CTA) ----
    for (int i = tid; i < 4 * 8 * 32; i += THREADS) {
        const int k = i >> 8, nt = (i >> 5) & 7, ln = i & 31;
        const int t = ln & 3, g = ln >> 2;
        w0f[i] = make_uint2(tf32_rna(W0[(8 * k + t) * 64 + nt * 8 + g]),
                            tf32_rna(W0[(8 * k + t + 4) * 64 + nt * 8 + g]));
    }
    for (int i = tid; i < 8 * 8 * 32; i += THREADS) {
        const int k = i >> 8, nt = (i >> 5) & 7, ln = i & 31;
        const int t = ln & 3, g = ln >> 2;
        w1f[i] = make_uint2(tf32_rna(W1[(8 * k + t) * 64 + nt * 8 + g]),
                            tf32_rna(W1[(8 * k + t + 4) * 64 + nt * 8 + g]));
    }
    for (int i = tid; i < 3 * 64; i += THREADS) {
        const int j = i >> 6, c = i & 63;
        w2s[i] = W2[c * 3 + j];
    }
    __syncthreads();

    const int wid  = tid >> 5;
    const int lane = tid & 31;
    const int t    = lane & 3;          // threadIDInGroup
    const int g    = lane >> 2;         // groupID
    const int h    = lane & 1;          // level parity for encode
    const int pl   = lane >> 1;         // point within tile for encode
    uint32_t* buf  = dynscr + wid * (SCR_ROWS * 64);
    const int wg   = blockIdx.x * WARPS + wid;

    // floor(16 * 1.5^l): even levels / odd levels
    const int res_e[8] = {16, 36, 81, 182, 410, 922, 2075, 4670};
    const int res_o[8] = {24, 54, 121, 273, 615, 1383, 3113, 7006};

    for (int it = 0; it < ITERS; it++) {
        const int base = wg * PPW + it * PPI;
        __syncwarp();

        // ---- encode: 2 tiles of 16 points; thread (h,pl) does point pl, parity-h levels ----
#pragma unroll
        for (int tt = 0; tt < 2; tt++) {
            const float2 p = __ldg(&xy[base + tt * 16 + pl]);
            const float c0 = p.x, c1 = p.y;
            const int row = tt * 16 + pl;
#pragma unroll
            for (int lp = 0; lp < 8; lp++) {
                const int res   = h ? res_o[lp] : res_e[lp];
                const int level = 2 * lp + h;
                const bool dense = (lp < 5);   // levels 0..9 dense

                const float fres = (float)res;
                const float px = c0 * fres;
                const float py = c1 * fres;
                const float fx = floorf(px);
                const float fy = floorf(py);
                const float wx = px - fx;
                const float wy = py - fy;
                const int ix = (int)fx;
                const int iy = (int)fy;

                int i00, i01, i10, i11;
                if (dense) {
                    const int r1 = res + 1;
                    i00 = ix + iy * r1;
                    i01 = i00 + r1;
                    i10 = i00 + 1;
                    i11 = i01 + 1;
                } else {
                    const uint32_t P = 2654435761u;
                    const uint32_t ux = (uint32_t)ix;
                    const uint32_t uy = (uint32_t)iy;
                    const uint32_t hy0 = uy * P;
                    const uint32_t hy1 = (uy + 1u) * P;
                    i00 = (int)((ux        ^ hy0) & (uint32_t)(TBL - 1));
                    i01 = (int)((ux        ^ hy1) & (uint32_t)(TBL - 1));
                    i10 = (int)(((ux + 1u) ^ hy0) & (uint32_t)(TBL - 1));
                    i11 = (int)(((ux + 1u) ^ hy1) & (uint32_t)(TBL - 1));
                }

                const float2* lt = tab + (size_t)level * TBL;
                const float2 a00 = __ldg(lt + i00);
                const float2 a01 = __ldg(lt + i01);
                const float2 a10 = __ldg(lt + i10);
                const float2 a11 = __ldg(lt + i11);

                const float w00 = (1.0f - wx) * (1.0f - wy);
                const float w01 = (1.0f - wx) * wy;
                const float w10 = wx * (1.0f - wy);
                const float w11 = wx * wy;

                const float f0 = a00.x * w00 + a01.x * w01 + a10.x * w10 + a11.x * w11;
                const float f1 = a00.y * w00 + a01.y * w01 + a10.y * w10 + a11.y * w11;

                *reinterpret_cast<uint2*>(&buf[sx(row, 4 * lp + 2 * h)]) =
                    make_uint2(tf32_rna(f0), tf32_rna(f1));
            }
        }
        __syncwarp();

        // ---- layer 0: two (16x32)@(32x64) tiles sharing B fragments ----
        float C[2][8][4];
#pragma unroll
        for (int tt = 0; tt < 2; tt++)
#pragma unroll
            for (int nt = 0; nt < 8; nt++)
#pragma unroll
                for (int j = 0; j < 4; j++) C[tt][nt][j] = 0.0f;

#pragma unroll
        for (int k = 0; k < 4; k++) {
            uint32_t a[2][4];
#pragma unroll
            for (int tt = 0; tt < 2; tt++) {
                const int r0 = tt * 16 + g, r1 = r0 + 8;
                a[tt][0] = buf[sx(r0, 8 * k + t)];
                a[tt][1] = buf[sx(r1, 8 * k + t)];
                a[tt][2] = buf[sx(r0, 8 * k + t + 4)];
                a[tt][3] = buf[sx(r1, 8 * k + t + 4)];
            }
#pragma unroll
            for (int nt = 0; nt < 8; nt++) {
                const uint2 b = w0f[(k * 8 + nt) * 32 + lane];
                mma8(C[0][nt], a[0][0], a[0][1], a[0][2], a[0][3], b.x, b.y);
                mma8(C[1][nt], a[1][0], a[1][1], a[1][2], a[1][3], b.x, b.y);
            }
        }
        __syncwarp();

        // ---- relu + store h0 for both tiles ----
#pragma unroll
        for (int tt = 0; tt < 2; tt++) {
            const int r0 = tt * 16 + g, r1 = r0 + 8;
#pragma unroll
            for (int nt = 0; nt < 8; nt++) {
                const int col = nt * 8 + 2 * t;
                *reinterpret_cast<uint2*>(&buf[sx(r0, col)]) =
                    make_uint2(tf32_rna(fmaxf(C[tt][nt][0], 0.0f)),
                               tf32_rna(fmaxf(C[tt][nt][1], 0.0f)));
                *reinterpret_cast<uint2*>(&buf[sx(r1, col)]) =
                    make_uint2(tf32_rna(fmaxf(C[tt][nt][2], 0.0f)),
                               tf32_rna(fmaxf(C[tt][nt][3], 0.0f)));
            }
        }
        __syncwarp();

        // ---- layer 1: two (16x64)@(64x64) tiles sharing B fragments ----
#pragma unroll
        for (int tt = 0; tt < 2; tt++)
#pragma unroll
            for (int nt = 0; nt < 8; nt++)
#pragma unroll
                for (int j = 0; j < 4; j++) C[tt][nt][j] = 0.0f;

#pragma unroll
        for (int k = 0; k < 8; k++) {
            uint32_t a[2][4];
#pragma unroll
            for (int tt = 0; tt < 2; tt++) {
                const int r0 = tt * 16 + g, r1 = r0 + 8;
                a[tt][0] = buf[sx(r0, 8 * k + t)];
                a[tt][1] = buf[sx(r1, 8 * k + t)];
                a[tt][2] = buf[sx(r0, 8 * k + t + 4)];
                a[tt][3] = buf[sx(r1, 8 * k + t + 4)];
            }
#pragma unroll
            for (int nt = 0; nt < 8; nt++) {
                const uint2 b = w1f[(k * 8 + nt) * 32 + lane];
                mma8(C[0][nt], a[0][0], a[0][1], a[0][2], a[0][3], b.x, b.y);
                mma8(C[1][nt], a[1][0], a[1][1], a[1][2], a[1][3], b.x, b.y);
            }
        }

        // ---- epilogue: relu + (64x3), w2 float2 loads shared by both tiles ----
        float acc[2][2][3];
#pragma unroll
        for (int tt = 0; tt < 2; tt++)
#pragma unroll
            for (int r = 0; r < 2; r++)
#pragma unroll
                for (int j = 0; j < 3; j++) acc[tt][r][j] = 0.0f;

#pragma unroll
        for (int nt = 0; nt < 8; nt++) {
            const int cA = nt * 8 + 2 * t;
            float2 w[3];
#pragma unroll
            for (int j = 0; j < 3; j++)
                w[j] = *reinterpret_cast<const float2*>(&w2s[j * 64 + cA]);
#pragma unroll
            for (int tt = 0; tt < 2; tt++) {
                const float vA0 = fmaxf(C[tt][nt][0], 0.0f);
                const float vB0 = fmaxf(C[tt][nt][1], 0.0f);
                const float vA1 = fmaxf(C[tt][nt][2], 0.0f);
                const float vB1 = fmaxf(C[tt][nt][3], 0.0f);
#pragma unroll
                for (int j = 0; j < 3; j++) {
                    acc[tt][0][j] += vA0 * w[j].x + vB0 * w[j].y;
                    acc[tt][1][j] += vA1 * w[j].x + vB1 * w[j].y;
                }
            }
        }
#pragma unroll
        for (int tt = 0; tt < 2; tt++)
#pragma unroll
            for (int r = 0; r < 2; r++)
#pragma unroll
                for (int j = 0; j < 3; j++) {
                    float v = acc[tt][r][j];
                    v += __shfl_xor_sync(0xffffffffu, v, 1);
                    v += __shfl_xor_sync(0xffffffffu, v, 2);
                    acc[tt][r][j] = v;
                }
        if (t == 0) {
#pragma unroll
            for (int tt = 0; tt < 2; tt++)
#pragma unroll
                for (int r = 0; r < 2; r++) {
                    const int pid = base + tt * 16 + g + 8 * r;
#pragma unroll
                    for (int j = 0; j < 3; j++) out[j * NPTS + pid] = acc[tt][r][j];
                }
        }
    }
}

}  // namespace

extern "C" void kernel_launch(void* const* d_in, const int* in_sizes, int n_in,
                              void* d_out, int out_size) {
    (void)in_sizes; (void)n_in; (void)out_size;
    const float2* xy  = (const float2*)d_in[0];
    const float2* tab = (const float2*)d_in[1];
    const float*  W0  = (const float*)d_in[2];
    const float*  W1  = (const float*)d_in[3];
    const float*  W2  = (const float*)d_in[4];
    float* out = (float*)d_out;

    cudaFuncSetAttribute(ngp_mma_kernel,
                         cudaFuncAttributeMaxDynamicSharedMemorySize, DYN_SMEM);
    ngp_mma_kernel<<<GRID, THREADS, DYN_SMEM>>>(xy, tab, W0, W1, W2, out);
}